// round 3
// baseline (speedup 1.0000x reference)
#include <cuda_runtime.h>
#include <cuda_bf16.h>
#include <math.h>

#define BB 64
#define TT 1024
#define FF 128
#define UU 256

typedef unsigned long long ull;

// ---------------------------------------------------------------------------
// Packed f32x2 helpers (sm_100+): two independent fp32 FMAs per instruction,
// exact fp32 arithmetic (NOT reduced precision).
// ---------------------------------------------------------------------------
__device__ __forceinline__ void ffma2(ull &d, ull a, ull b) {
    asm("fma.rn.f32x2 %0, %1, %2, %0;" : "+l"(d) : "l"(a), "l"(b));
}
__device__ __forceinline__ ull packf2(float lo, float hi) {
    ull r;
    asm("mov.b64 %0, {%1, %2};" : "=l"(r) : "f"(lo), "f"(hi));
    return r;
}
__device__ __forceinline__ float f2lo(ull v) { return __uint_as_float((unsigned)v); }
__device__ __forceinline__ float f2hi(ull v) { return __uint_as_float((unsigned)(v >> 32)); }

// ---------------------------------------------------------------------------
// Kernel 1: projection  h[t,b,u] = sum_f inputs[b,t,f] * R[f,u]
// Written into d_out ([T,B,U]); the recurrence kernel overwrites in place.
// Grid (T/32, B), 256 threads/CTA.
// Smem: R pair-packed over f as f32x2 (128 KB) + 32 input rows (16 KB).
// Thread tile: 8 t-rows x 4 u-cols -> 32 f32x2 accumulators.
// ---------------------------------------------------------------------------
#define PROJ_SMEM (128 * 1024 + 32 * 128 * 4)

__global__ __launch_bounds__(256, 1)
void proj_kernel(const float* __restrict__ inp, const float* __restrict__ R,
                 float* __restrict__ out)
{
    extern __shared__ ull smem_p[];
    ull*   Rs  = smem_p;                    // 16384 ull: Rs[p*256+u] = (R[2p][u], R[2p+1][u])
    float* xin = (float*)(smem_p + 16384);  // 32 rows x 128 floats

    const int tid = threadIdx.x;
    const int b   = blockIdx.y;
    const int t0  = blockIdx.x * 32;

    // Fill Rs: iteration i handles f-pair i for u = tid (coalesced over u).
    #pragma unroll 1
    for (int i = 0; i < 64; ++i) {
        Rs[i * 256 + tid] = packf2(R[(2 * i) * UU + tid], R[(2 * i + 1) * UU + tid]);
    }
    // Fill xin: 32 contiguous input rows = 4096 floats = 1024 float4.
    {
        const float4* src = (const float4*)(inp + (size_t)b * TT * FF + (size_t)t0 * FF);
        float4* dst = (float4*)xin;
        #pragma unroll
        for (int i = 0; i < 4; ++i) dst[tid + i * 256] = src[tid + i * 256];
    }
    __syncthreads();

    const int uu = tid & 63;        // u-group: covers u0..u0+3
    const int rg = tid >> 6;        // row-group: rows rg*8 .. rg*8+7
    const int u0 = uu * 4;
    const ull* xr = (const ull*)xin;   // xr[row*64 + p] = (x[2p], x[2p+1])

    ull acc[32];
    #pragma unroll
    for (int i = 0; i < 32; ++i) acc[i] = 0ull;

    #pragma unroll 4
    for (int p = 0; p < 64; ++p) {
        ull w0 = Rs[p * 256 + u0 + 0];
        ull w1 = Rs[p * 256 + u0 + 1];
        ull w2 = Rs[p * 256 + u0 + 2];
        ull w3 = Rs[p * 256 + u0 + 3];
        #pragma unroll
        for (int ri = 0; ri < 8; ++ri) {
            ull xv = xr[(rg * 8 + ri) * 64 + p];   // warp-broadcast
            ffma2(acc[ri * 4 + 0], xv, w0);
            ffma2(acc[ri * 4 + 1], xv, w1);
            ffma2(acc[ri * 4 + 2], xv, w2);
            ffma2(acc[ri * 4 + 3], xv, w3);
        }
    }

    #pragma unroll
    for (int ri = 0; ri < 8; ++ri) {
        int t = t0 + rg * 8 + ri;
        float4 v;
        v.x = f2lo(acc[ri * 4 + 0]) + f2hi(acc[ri * 4 + 0]);
        v.y = f2lo(acc[ri * 4 + 1]) + f2hi(acc[ri * 4 + 1]);
        v.z = f2lo(acc[ri * 4 + 2]) + f2hi(acc[ri * 4 + 2]);
        v.w = f2lo(acc[ri * 4 + 3]) + f2hi(acc[ri * 4 + 3]);
        *(float4*)(out + (size_t)t * (BB * UU) + (size_t)b * UU + u0) = v;
    }
}

// ---------------------------------------------------------------------------
// Kernel 2: recurrence. One CTA per batch element (64 CTAs x 512 threads).
//   x_t = tanh(h[t] + x_{t-1} @ W + bias)
// Thread (ug = tid&63, kq = tid>>6) covers u in [4*ug, 4*ug+4),
// k in [32*kq, 32*kq+32) = 16 k-pairs:
//   pairs 0..11  -> registers (96 regs/thread, 192 KB/CTA)
//   pairs 12..15 -> smem Wsm (64 KB/CTA), conflict-free [slot*512 + tid]
// State x lives in smem as aligned f32 (read as f32x2 pairs, warp-broadcast).
// Per-step: FMA loop -> partial[kq][u] -> barrier -> 256 threads finalize
// (8-way sum + h + bias, tanhf) -> write state + output -> barrier.
// h[t] is read from d_out (written by proj) and overwritten in place by x_t.
// ---------------------------------------------------------------------------
#define REC_SMEM (64 * 1024 + 256 * 4 + 8 * 256 * 4)

__global__ __launch_bounds__(512, 1)
void rec_kernel(const float* __restrict__ W, const float* __restrict__ bias,
                const float* __restrict__ x0, float* out)
{
    extern __shared__ ull smem_r[];
    ull*   Wsm     = smem_r;                    // 16 slots * 512 ull = 64 KB
    float* sxf     = (float*)(smem_r + 16 * 512);  // 256 floats (state)
    float* partial = sxf + 256;                    // 8 * 256 floats

    const int tid = threadIdx.x;
    const int b   = blockIdx.x;
    const int ug  = tid & 63;
    const int kq  = tid >> 6;        // 0..7
    const int u0  = ug * 4;
    const int k0  = kq * 32;

    // --- Load W partition: pairs over k, 4 u columns per thread ---
    ull wreg[4][12];
    #pragma unroll
    for (int p = 0; p < 16; ++p) {
        float4 va = *(const float4*)(W + (size_t)(k0 + 2 * p)     * UU + u0);
        float4 vb = *(const float4*)(W + (size_t)(k0 + 2 * p + 1) * UU + u0);
        ull w0 = packf2(va.x, vb.x);
        ull w1 = packf2(va.y, vb.y);
        ull w2 = packf2(va.z, vb.z);
        ull w3 = packf2(va.w, vb.w);
        if (p < 12) {
            wreg[0][p] = w0; wreg[1][p] = w1; wreg[2][p] = w2; wreg[3][p] = w3;
        } else {
            int p4 = p - 12;
            Wsm[(p4 * 4 + 0) * 512 + tid] = w0;
            Wsm[(p4 * 4 + 1) * 512 + tid] = w1;
            Wsm[(p4 * 4 + 2) * 512 + tid] = w2;
            Wsm[(p4 * 4 + 3) * 512 + tid] = w3;
        }
    }

    float breg = 0.f;
    if (tid < 256) {
        breg = bias[tid];
        sxf[tid] = x0[tid];      // initial state (broadcast across batch)
    }
    __syncthreads();

    float* outp = out + (size_t)b * UU + tid;   // dereferenced only when tid < 256
    const ull* sxp = (const ull*)sxf;           // sxp[i] = (x[2i], x[2i+1])

    for (int t = 0; t < TT; ++t) {
        // Prefetch h[t,b,u] — latency hidden under the FMA loop below.
        float hreg = 0.f;
        if (tid < 256) hreg = outp[(size_t)t * (BB * UU)];

        ull acc0 = 0, acc1 = 0, acc2 = 0, acc3 = 0;
        #pragma unroll
        for (int p = 0; p < 12; ++p) {
            ull xp = sxp[kq * 16 + p];
            ffma2(acc0, xp, wreg[0][p]);
            ffma2(acc1, xp, wreg[1][p]);
            ffma2(acc2, xp, wreg[2][p]);
            ffma2(acc3, xp, wreg[3][p]);
        }
        #pragma unroll
        for (int p4 = 0; p4 < 4; ++p4) {
            ull xp = sxp[kq * 16 + 12 + p4];
            ffma2(acc0, xp, Wsm[(p4 * 4 + 0) * 512 + tid]);
            ffma2(acc1, xp, Wsm[(p4 * 4 + 1) * 512 + tid]);
            ffma2(acc2, xp, Wsm[(p4 * 4 + 2) * 512 + tid]);
            ffma2(acc3, xp, Wsm[(p4 * 4 + 3) * 512 + tid]);
        }

        float4 ps;
        ps.x = f2lo(acc0) + f2hi(acc0);
        ps.y = f2lo(acc1) + f2hi(acc1);
        ps.z = f2lo(acc2) + f2hi(acc2);
        ps.w = f2lo(acc3) + f2hi(acc3);
        *(float4*)(partial + kq * 256 + u0) = ps;   // STS.128, conflict-free
        __syncthreads();

        if (tid < 256) {
            float y = hreg + breg;
            #pragma unroll
            for (int j = 0; j < 8; ++j) y += partial[j * 256 + tid];
            float x = tanhf(y);
            sxf[tid] = x;                           // new state
            outp[(size_t)t * (BB * UU)] = x;        // overwrite h[t] with x_t
        }
        __syncthreads();
    }
}

// ---------------------------------------------------------------------------
// Launch. Inputs (metadata order): inputs[B,T,F], R[F,U], W[U,U], bias[U],
// x0[U]. Output: float32 states[T,B,U].
// ---------------------------------------------------------------------------
extern "C" void kernel_launch(void* const* d_in, const int* in_sizes, int n_in,
                              void* d_out, int out_size) {
    const float* inp  = (const float*)d_in[0];
    const float* R    = (const float*)d_in[1];
    const float* W    = (const float*)d_in[2];
    const float* bias = (const float*)d_in[3];
    const float* x0   = (const float*)d_in[4];
    float* out = (float*)d_out;

    cudaFuncSetAttribute(proj_kernel, cudaFuncAttributeMaxDynamicSharedMemorySize, PROJ_SMEM);
    cudaFuncSetAttribute(rec_kernel,  cudaFuncAttributeMaxDynamicSharedMemorySize, REC_SMEM);

    proj_kernel<<<dim3(TT / 32, BB), 256, PROJ_SMEM>>>(inp, R, out);
    rec_kernel<<<BB, 512, REC_SMEM>>>(W, bias, x0, out);
}

// round 7
// speedup vs baseline: 1.6014x; 1.6014x over previous
#include <cuda_runtime.h>
#include <cuda_bf16.h>
#include <math.h>

#define BB 64
#define TT 1024
#define FF 128
#define UU 256

typedef unsigned long long ull;

// ---------------------------------------------------------------------------
// Packed f32x2 helpers (sm_100+): two independent fp32 FMAs per instruction,
// exact fp32 arithmetic (NOT reduced precision).
// ---------------------------------------------------------------------------
__device__ __forceinline__ void ffma2(ull &d, ull a, ull b) {
    asm("fma.rn.f32x2 %0, %1, %2, %0;" : "+l"(d) : "l"(a), "l"(b));
}
__device__ __forceinline__ ull packf2(float lo, float hi) {
    ull r;
    asm("mov.b64 %0, {%1, %2};" : "=l"(r) : "f"(lo), "f"(hi));
    return r;
}
__device__ __forceinline__ float f2lo(ull v) { return __uint_as_float((unsigned)v); }
__device__ __forceinline__ float f2hi(ull v) { return __uint_as_float((unsigned)(v >> 32)); }

// Fast tanh via MUFU.EX2 + MUFU.RCP. For the y-range of this recurrence
// (|y| < ~2), rel err ~1e-6; exact saturation for large |y|.
__device__ __forceinline__ float tanh_fast(float y) {
    float e = __expf(2.0f * y);
    return 1.0f - __fdividef(2.0f, e + 1.0f);
}

// ---------------------------------------------------------------------------
// Kernel 1: projection  h[t,b,u] = sum_f inputs[b,t,f] * R[f,u]
// Written into d_out ([T,B,U]); the recurrence kernel overwrites in place.
// Grid (T/32, B), 256 threads/CTA. (unchanged from R3 — ~70us, not critical)
// ---------------------------------------------------------------------------
#define PROJ_SMEM (128 * 1024 + 32 * 128 * 4)

__global__ __launch_bounds__(256, 1)
void proj_kernel(const float* __restrict__ inp, const float* __restrict__ R,
                 float* __restrict__ out)
{
    extern __shared__ ull smem_p[];
    ull*   Rs  = smem_p;                    // 16384 ull: Rs[p*256+u] = (R[2p][u], R[2p+1][u])
    float* xin = (float*)(smem_p + 16384);  // 32 rows x 128 floats

    const int tid = threadIdx.x;
    const int b   = blockIdx.y;
    const int t0  = blockIdx.x * 32;

    #pragma unroll 1
    for (int i = 0; i < 64; ++i) {
        Rs[i * 256 + tid] = packf2(R[(2 * i) * UU + tid], R[(2 * i + 1) * UU + tid]);
    }
    {
        const float4* src = (const float4*)(inp + (size_t)b * TT * FF + (size_t)t0 * FF);
        float4* dst = (float4*)xin;
        #pragma unroll
        for (int i = 0; i < 4; ++i) dst[tid + i * 256] = src[tid + i * 256];
    }
    __syncthreads();

    const int uu = tid & 63;
    const int rg = tid >> 6;
    const int u0 = uu * 4;
    const ull* xr = (const ull*)xin;

    ull acc[32];
    #pragma unroll
    for (int i = 0; i < 32; ++i) acc[i] = 0ull;

    #pragma unroll 4
    for (int p = 0; p < 64; ++p) {
        ull w0 = Rs[p * 256 + u0 + 0];
        ull w1 = Rs[p * 256 + u0 + 1];
        ull w2 = Rs[p * 256 + u0 + 2];
        ull w3 = Rs[p * 256 + u0 + 3];
        #pragma unroll
        for (int ri = 0; ri < 8; ++ri) {
            ull xv = xr[(rg * 8 + ri) * 64 + p];
            ffma2(acc[ri * 4 + 0], xv, w0);
            ffma2(acc[ri * 4 + 1], xv, w1);
            ffma2(acc[ri * 4 + 2], xv, w2);
            ffma2(acc[ri * 4 + 3], xv, w3);
        }
    }

    #pragma unroll
    for (int ri = 0; ri < 8; ++ri) {
        int t = t0 + rg * 8 + ri;
        float4 v;
        v.x = f2lo(acc[ri * 4 + 0]) + f2hi(acc[ri * 4 + 0]);
        v.y = f2lo(acc[ri * 4 + 1]) + f2hi(acc[ri * 4 + 1]);
        v.z = f2lo(acc[ri * 4 + 2]) + f2hi(acc[ri * 4 + 2]);
        v.w = f2lo(acc[ri * 4 + 3]) + f2hi(acc[ri * 4 + 3]);
        *(float4*)(out + (size_t)t * (BB * UU) + (size_t)b * UU + u0) = v;
    }
}

// ---------------------------------------------------------------------------
// Kernel 2: recurrence. One CTA per batch element (64 CTAs x 512 threads).
//   x_t = tanh(h[t] + x_{t-1} @ W + bias)
// Thread (ug = tid&63, kq = tid>>6) covers u in [4*ug, 4*ug+4),
// k in [32*kq, 32*kq+32) = 16 k-pairs:
//   pairs 0..11  -> registers (96 regs/thread, 192 KB/CTA)
//   pairs 12..15 -> smem as ulonglong2[8][512]: slot (q*2+half) holds the
//                   f32x2 weights for k-pair 12+q, u-cols {2*half, 2*half+1}.
//                   One conflict-free LDS.128 per (k-pair, u-half).
// Per step: FMA loop -> partial[kq][u] (STS.128) -> bar -> 256-thread tree
// reduce + fast tanh -> state + output -> bar.
// ---------------------------------------------------------------------------
#define REC_SMEM (64 * 1024 + 256 * 4 + 8 * 256 * 4)

__global__ __launch_bounds__(512, 1)
void rec_kernel(const float* __restrict__ W, const float* __restrict__ bias,
                const float* __restrict__ x0, float* out)
{
    extern __shared__ ull smem_r[];
    ulonglong2* Wsm2   = (ulonglong2*)smem_r;          // 8 slots * 512 ull2 = 64 KB
    float*      sxf    = (float*)(smem_r + 8192);      // 256 floats (state)
    float*      partial = sxf + 256;                   // 8 * 256 floats

    const int tid = threadIdx.x;
    const int b   = blockIdx.x;
    const int kq  = tid >> 6;        // 0..7
    const int u0  = (tid & 63) * 4;
    const int k0  = kq * 32;

    // --- Load W partition ---
    ull wreg[4][12];
    #pragma unroll
    for (int p = 0; p < 16; ++p) {
        float4 va = *(const float4*)(W + (size_t)(k0 + 2 * p)     * UU + u0);
        float4 vb = *(const float4*)(W + (size_t)(k0 + 2 * p + 1) * UU + u0);
        ull w0 = packf2(va.x, vb.x);
        ull w1 = packf2(va.y, vb.y);
        ull w2 = packf2(va.z, vb.z);
        ull w3 = packf2(va.w, vb.w);
        if (p < 12) {
            wreg[0][p] = w0; wreg[1][p] = w1; wreg[2][p] = w2; wreg[3][p] = w3;
        } else {
            int q = p - 12;
            Wsm2[(q * 2 + 0) * 512 + tid] = make_ulonglong2(w0, w1);
            Wsm2[(q * 2 + 1) * 512 + tid] = make_ulonglong2(w2, w3);
        }
    }

    float breg = 0.f;
    if (tid < 256) {
        breg = bias[tid];
        sxf[tid] = x0[tid];
    }
    __syncthreads();

    float* outp = out + (size_t)b * UU + tid;            // used only when tid < 256
    const ulonglong2* sx2 = (const ulonglong2*)sxf + kq * 8;  // this kq's 16 pairs

    for (int t = 0; t < TT; ++t) {
        // Prefetch h[t,b,u]; DRAM/L2 latency hides under the FMA loop.
        float hreg = 0.f;
        if (tid < 256) hreg = outp[(size_t)t * (BB * UU)];

        ull acc0 = 0, acc1 = 0, acc2 = 0, acc3 = 0;

        // k-pairs 0..11: register-resident W
        #pragma unroll
        for (int i = 0; i < 6; ++i) {
            ulonglong2 xp = sx2[i];                       // LDS.128, warp-broadcast
            ffma2(acc0, xp.x, wreg[0][2 * i]);
            ffma2(acc1, xp.x, wreg[1][2 * i]);
            ffma2(acc2, xp.x, wreg[2][2 * i]);
            ffma2(acc3, xp.x, wreg[3][2 * i]);
            ffma2(acc0, xp.y, wreg[0][2 * i + 1]);
            ffma2(acc1, xp.y, wreg[1][2 * i + 1]);
            ffma2(acc2, xp.y, wreg[2][2 * i + 1]);
            ffma2(acc3, xp.y, wreg[3][2 * i + 1]);
        }
        // k-pairs 12..15: smem-resident W, conflict-free LDS.128
        #pragma unroll
        for (int i = 0; i < 2; ++i) {
            ulonglong2 xp = sx2[6 + i];
            {
                ulonglong2 wa0 = Wsm2[(i * 4 + 0) * 512 + tid];  // k-pair 12+2i, u0/u1
                ulonglong2 wa1 = Wsm2[(i * 4 + 1) * 512 + tid];  // k-pair 12+2i, u2/u3
                ffma2(acc0, xp.x, wa0.x);
                ffma2(acc1, xp.x, wa0.y);
                ffma2(acc2, xp.x, wa1.x);
                ffma2(acc3, xp.x, wa1.y);
            }
            {
                ulonglong2 wb0 = Wsm2[(i * 4 + 2) * 512 + tid];  // k-pair 13+2i, u0/u1
                ulonglong2 wb1 = Wsm2[(i * 4 + 3) * 512 + tid];  // k-pair 13+2i, u2/u3
                ffma2(acc0, xp.y, wb0.x);
                ffma2(acc1, xp.y, wb0.y);
                ffma2(acc2, xp.y, wb1.x);
                ffma2(acc3, xp.y, wb1.y);
            }
        }

        float4 ps;
        ps.x = f2lo(acc0) + f2hi(acc0);
        ps.y = f2lo(acc1) + f2hi(acc1);
        ps.z = f2lo(acc2) + f2hi(acc2);
        ps.w = f2lo(acc3) + f2hi(acc3);
        *(float4*)(partial + kq * 256 + u0) = ps;        // STS.128, conflict-free
        __syncthreads();

        if (tid < 256) {
            // Tree reduction over the 8 kq partials (conflict-free LDS.32)
            float s0 = partial[           tid] + partial[ 256 + tid];
            float s1 = partial[ 512 + tid] + partial[ 768 + tid];
            float s2 = partial[1024 + tid] + partial[1280 + tid];
            float s3 = partial[1536 + tid] + partial[1792 + tid];
            float y  = ((s0 + s1) + (s2 + s3)) + (hreg + breg);
            float x  = tanh_fast(y);
            sxf[tid] = x;                                // new state
            outp[(size_t)t * (BB * UU)] = x;             // overwrite h[t] with x_t
        }
        __syncthreads();
    }
}

// ---------------------------------------------------------------------------
// Launch. Inputs (metadata order): inputs[B,T,F], R[F,U], W[U,U], bias[U],
// x0[U]. Output: float32 states[T,B,U].
// ---------------------------------------------------------------------------
extern "C" void kernel_launch(void* const* d_in, const int* in_sizes, int n_in,
                              void* d_out, int out_size) {
    const float* inp  = (const float*)d_in[0];
    const float* R    = (const float*)d_in[1];
    const float* W    = (const float*)d_in[2];
    const float* bias = (const float*)d_in[3];
    const float* x0   = (const float*)d_in[4];
    float* out = (float*)d_out;

    cudaFuncSetAttribute(proj_kernel, cudaFuncAttributeMaxDynamicSharedMemorySize, PROJ_SMEM);
    cudaFuncSetAttribute(rec_kernel,  cudaFuncAttributeMaxDynamicSharedMemorySize, REC_SMEM);

    proj_kernel<<<dim3(TT / 32, BB), 256, PROJ_SMEM>>>(inp, R, out);
    rec_kernel<<<BB, 512, REC_SMEM>>>(W, bias, x0, out);
}